// round 13
// baseline (speedup 1.0000x reference)
#include <cuda_runtime.h>
#include <cuda_bf16.h>
#include <cstdint>
#include <cstddef>

#define H_DIM 1024
#define I_DIM 1024
#define C_DIM 64

typedef signed char s8;

// ---------------------------------------------------------------------------
// Static scratch (module-load allocated). 256B-aligned for 16B vector access.
// ---------------------------------------------------------------------------
#define ACT_ELEMS ((size_t)C_DIM * H_DIM * I_DIM)
__device__ __align__(256) s8 g_xq1[ACT_ELEMS];   // xT digits (later z digits)
__device__ __align__(256) s8 g_xq2[ACT_ELEMS];
__device__ __align__(256) s8 g_b1q1[ACT_ELEMS];  // stage1 out (later pT digits)
__device__ __align__(256) s8 g_b1q2[ACT_ELEMS];
__device__ __align__(256) s8 g_pq1[ACT_ELEMS];   // p_out digits (stage4 residual)
__device__ __align__(256) s8 g_pq2[ACT_ELEMS];
__device__ __align__(256) s8 g_wpq1[H_DIM * H_DIM];
__device__ __align__(256) s8 g_wpq2[H_DIM * H_DIM];
__device__ __align__(256) s8 g_plq1[I_DIM * I_DIM];
__device__ __align__(256) s8 g_plq2[I_DIM * I_DIM];
__device__ __align__(256) s8 g_wzq1[H_DIM * H_DIM];
__device__ __align__(256) s8 g_wzq2[H_DIM * H_DIM];
__device__ __align__(256) s8 g_zlq1[I_DIM * I_DIM];
__device__ __align__(256) s8 g_zlq2[I_DIM * I_DIM];
__device__ __align__(256) float g_swp[H_DIM];
__device__ __align__(256) float g_spl[I_DIM];
__device__ __align__(256) float g_swz[H_DIM];
__device__ __align__(256) float g_szl[I_DIM];
__device__ __align__(256) float g_sxs[C_DIM * I_DIM];   // per (c,i) scale of xT
__device__ __align__(256) float g_sxi[C_DIM * I_DIM];   // inverse scale

#define INV254  0.003937007874015748f   // 1/254
#define INV127  0.007874015748031496f   // 1/127

__device__ __forceinline__ float actf(float x) { return fminf(fmaxf(x, -1.0f), 1.0f); }

// 2-digit int8 quantization: v ~= (q1 + q2/254) / inv_s
// Digit 2 uses the FULL int8 range (rem in [-0.5,0.5] -> q2 in [-127,127]).
__device__ __forceinline__ void quant2(float v, float inv_s, s8& q1, s8& q2) {
    float t = v * inv_s;
    int a = __float2int_rn(t);
    a = max(-127, min(127, a));
    float rem = t - (float)a;
    int b = __float2int_rn(rem * 254.0f);
    b = max(-127, min(127, b));
    q1 = (s8)a; q2 = (s8)b;
}

// ---------------------------------------------------------------------------
// Prep kernels
// ---------------------------------------------------------------------------
template <int WPMODE>
__global__ void quant_w_kernel(const float* __restrict__ W, const float* __restrict__ Wd,
                               s8* __restrict__ O1, s8* __restrict__ O2,
                               float* __restrict__ S) {
    __shared__ float red[256];
    const int h = blockIdx.x;
    const int tid = threadIdx.x;
    float v[4];
    float mx = 0.0f;
#pragma unroll
    for (int j = 0; j < 4; ++j) {
        const int k = tid + j * 256;
        float t = W[h * 1024 + k];
        if (WPMODE) {
            if (k > h) t = 0.0f;
            else if (k == h) t = fminf(fmaxf(t, 0.0f), 1.0f) + Wd[h];
        }
        v[j] = t;
        mx = fmaxf(mx, fabsf(t));
    }
    red[tid] = mx;
    __syncthreads();
    for (int s = 128; s > 0; s >>= 1) {
        if (tid < s) red[tid] = fmaxf(red[tid], red[tid + s]);
        __syncthreads();
    }
    const float rmax = fmaxf(red[0], 1e-20f);
    const float scale = rmax / 127.0f;
    const float inv = 127.0f / rmax;
    if (tid == 0) S[h] = scale;
#pragma unroll
    for (int j = 0; j < 4; ++j) {
        const int k = tid + j * 256;
        s8 q1, q2; quant2(v[j], inv, q1, q2);
        O1[h * 1024 + k] = q1;
        O2[h * 1024 + k] = q2;
    }
}

// sx[c,i] = max_k |x[c,k,i] * act(pm[k,i])| -> scale + inverse
__global__ void scale_x_kernel(const float* __restrict__ x, const float* __restrict__ pm,
                               float* __restrict__ Ss, float* __restrict__ Si) {
    const int i = blockIdx.x * 256 + threadIdx.x;
    const int c = blockIdx.y;
    const size_t cOff = (size_t)c << 20;
    float mx = 0.0f;
    for (int k = 0; k < 1024; ++k) {
        const float m = actf(pm[(size_t)k * 1024 + i]);
        mx = fmaxf(mx, fabsf(x[cOff + (size_t)k * 1024 + i] * m));
    }
    mx = fmaxf(mx, 1e-20f);
    Ss[c * 1024 + i] = mx / 127.0f;
    Si[c * 1024 + i] = 127.0f / mx;
}

// XT[c,i,k] = x[c,k,i]*act(pm[k,i]) quantized with per-(c,i) scale
__global__ void convT_xq_kernel(const float* __restrict__ x, const float* __restrict__ pm,
                                const float* __restrict__ Si,
                                s8* __restrict__ T1, s8* __restrict__ T2) {
    __shared__ float t[32][33];
    const int i0 = blockIdx.x * 32, k0 = blockIdx.y * 32;
    const int c = blockIdx.z;
    const size_t cOff = (size_t)c << 20;
    const int tx = threadIdx.x, ty = threadIdx.y;
#pragma unroll
    for (int r = 0; r < 4; ++r) {
        const int k = k0 + ty + r * 8;
        const float m = actf(pm[(size_t)k * 1024 + i0 + tx]);
        t[ty + r * 8][tx] = x[cOff + (size_t)k * 1024 + i0 + tx] * m;
    }
    __syncthreads();
#pragma unroll
    for (int r = 0; r < 4; ++r) {
        const int i = i0 + ty + r * 8;
        const float inv = Si[c * 1024 + i];
        const float v = t[tx][ty + r * 8];
        s8 q1, q2; quant2(v, inv, q1, q2);
        T1[cOff + (size_t)i * 1024 + k0 + tx] = q1;
        T2[cOff + (size_t)i * 1024 + k0 + tx] = q2;
    }
}

// Transpose int8 digit pair planes: PT[c,i,h] = P[c,h,i]
__global__ void transP_q_kernel(const s8* __restrict__ P1, const s8* __restrict__ P2,
                                s8* __restrict__ T1, s8* __restrict__ T2) {
    __shared__ s8 t1[32][33], t2[32][33];
    const int i0 = blockIdx.x * 32, h0 = blockIdx.y * 32;
    const size_t cOff = (size_t)blockIdx.z << 20;
    const int tx = threadIdx.x, ty = threadIdx.y;
#pragma unroll
    for (int r = 0; r < 4; ++r) {
        const int h = h0 + ty + r * 8;
        t1[ty + r * 8][tx] = P1[cOff + (size_t)h * 1024 + i0 + tx];
        t2[ty + r * 8][tx] = P2[cOff + (size_t)h * 1024 + i0 + tx];
    }
    __syncthreads();
#pragma unroll
    for (int r = 0; r < 4; ++r) {
        const int i = i0 + ty + r * 8;
        T1[cOff + (size_t)i * 1024 + h0 + tx] = t1[tx][ty + r * 8];
        T2[cOff + (size_t)i * 1024 + h0 + tx] = t2[tx][ty + r * 8];
    }
}

// ---------------------------------------------------------------------------
// mma / ldmatrix / cp.async helpers (base ISA, valid on target sm_103)
// ---------------------------------------------------------------------------
__device__ __forceinline__ void imma16832(int* d, const uint32_t* a, const uint32_t* b) {
    asm volatile(
        "mma.sync.aligned.m16n8k32.row.col.s32.s8.s8.s32 "
        "{%0,%1,%2,%3}, {%4,%5,%6,%7}, {%8,%9}, {%0,%1,%2,%3};"
        : "+r"(d[0]), "+r"(d[1]), "+r"(d[2]), "+r"(d[3])
        : "r"(a[0]), "r"(a[1]), "r"(a[2]), "r"(a[3]), "r"(b[0]), "r"(b[1]));
}
__device__ __forceinline__ void ldm_x4(uint32_t* r, uint32_t addr) {
    asm volatile("ldmatrix.sync.aligned.m8n8.x4.shared.b16 {%0,%1,%2,%3}, [%4];"
                 : "=r"(r[0]), "=r"(r[1]), "=r"(r[2]), "=r"(r[3]) : "r"(addr));
}
__device__ __forceinline__ void cp16(uint32_t dst, const void* src) {
    asm volatile("cp.async.cg.shared.global [%0], [%1], 16;" :: "r"(dst), "l"(src) : "memory");
}
__device__ __forceinline__ uint32_t smem_u32(const void* p) {
    uint32_t a;
    asm("{ .reg .u64 t; cvta.to.shared.u64 t, %1; cvt.u32.u64 %0, t; }" : "=r"(a) : "l"(p));
    return a;
}

// ---------------------------------------------------------------------------
// int8 GEMM (exact 2-digit product):
//   D[m,n] = sA_m*sB_n*(P1 + (P2 + P4/254)/254)
//   P1 = sum q1A*q1B, P2 = sum (q1A*q2B + q2A*q1B), P4 = sum q2A*q2B
// int32 accumulation exact (|acc| <= 127^2*1024 < 2^24).
// CTA tile 128x64, BK=32 bytes, 8 warps (4M x 2N), warp tile 32x32,
// 3-stage cp.async pipeline, 48B-pitch smem (conflict-free ldmatrix).
// APC/BPC: per-channel operand. TRI: triangular k-skip (stage 1).
// EPI: 0 = act -> digit pair; 1 = act(+bias) -> digit pair; 2 = act(+bias)+res -> f32.
// SAARR/SBARR: per-row scale array (else fixed 1/127).
// ---------------------------------------------------------------------------
#define PITCH 48
#define A_TILE (128 * PITCH)            // 6144
#define B_TILE (64 * PITCH)             // 3072
#define STAGE_B (2 * A_TILE + 2 * B_TILE)  // 18432
#define NSTAGE 3

template <int APC, int BPC, int TRI, int EPI, int SAARR, int SBARR>
__global__ __launch_bounds__(256, 1)
void gemm_imma(const s8* __restrict__ A1, const s8* __restrict__ A2,
               const s8* __restrict__ B1, const s8* __restrict__ B2,
               const float* __restrict__ sA, const float* __restrict__ sB,
               const float* __restrict__ bias,
               const s8* __restrict__ Rq1, const s8* __restrict__ Rq2,
               s8* __restrict__ Oq1, s8* __restrict__ Oq2,
               float* __restrict__ Of)
{
    extern __shared__ char smem[];
    const uint32_t sb = smem_u32(smem);
    const int tid = threadIdx.x;
    const int wid = tid >> 5;
    const int lane = tid & 31;
    const int gID = lane >> 2;
    const int tg  = lane & 3;
    const int wm = wid & 3;          // 4 warps over M (32 rows each)
    const int wn = wid >> 2;         // 2 warps over N (32 cols each)
    const int n0 = blockIdx.x * 64;
    const int m0 = blockIdx.y * 128;
    const size_t cOff = (size_t)blockIdx.z << 20;

    const int nch = TRI ? (blockIdx.y + 1) * 4 : 32;   // 32-byte K chunks

    const s8* pA1 = A1 + (APC ? cOff : 0) + (size_t)m0 * 1024;
    const s8* pA2 = A2 + (APC ? cOff : 0) + (size_t)m0 * 1024;
    const s8* pB1 = B1 + (BPC ? cOff : 0) + (size_t)n0 * 1024;
    const s8* pB2 = B2 + (BPC ? cOff : 0) + (size_t)n0 * 1024;

    auto issue = [&](int kc, int st) {
        const uint32_t base = sb + st * STAGE_B;
        const int row = tid >> 1;
        const int h = tid & 1;
        const size_t so = (size_t)row * 1024 + kc * 32 + h * 16;
        cp16(base + row * PITCH + h * 16, pA1 + so);
        cp16(base + A_TILE + row * PITCH + h * 16, pA2 + so);
        if (tid < 128) {
            cp16(base + 2 * A_TILE + row * PITCH + h * 16, pB1 + so);
            cp16(base + 2 * A_TILE + B_TILE + row * PITCH + h * 16, pB2 + so);
        }
        asm volatile("cp.async.commit_group;" ::: "memory");
    };

    // ldmatrix lane-address offsets (within a tile, pitch 48)
    const uint32_t a_off = (uint32_t)((wm * 32 + (lane & 7) + ((lane >> 3) & 1) * 8) * PITCH
                                      + (lane >> 4) * 16);
    const uint32_t b_off = (uint32_t)((wn * 32 + (lane & 7) + ((lane >> 4) & 1) * 8) * PITCH
                                      + ((lane >> 3) & 1) * 16);

    int acc1[2][4][4], acc2[2][4][4], acc4[2][4][4];
#pragma unroll
    for (int mt = 0; mt < 2; ++mt)
#pragma unroll
        for (int nt = 0; nt < 4; ++nt)
#pragma unroll
            for (int r = 0; r < 4; ++r) {
                acc1[mt][nt][r] = 0; acc2[mt][nt][r] = 0; acc4[mt][nt][r] = 0;
            }

    issue(0, 0);
    issue(1, 1);

    for (int kc = 0; kc < nch; ++kc) {
        if (kc + 1 < nch) {
            asm volatile("cp.async.wait_group 1;" ::: "memory");
        } else {
            asm volatile("cp.async.wait_group 0;" ::: "memory");
        }
        __syncthreads();
        if (kc + 2 < nch) issue(kc + 2, (kc + 2) % NSTAGE);

        const uint32_t bA1 = sb + (kc % NSTAGE) * STAGE_B;
        const uint32_t bA2 = bA1 + A_TILE;
        const uint32_t bB1 = bA1 + 2 * A_TILE;
        const uint32_t bB2 = bB1 + B_TILE;

        uint32_t a1f[2][4], a2f[2][4], bf1[4][2], bf2[4][2];
#pragma unroll
        for (int mt = 0; mt < 2; ++mt) {
            ldm_x4(a1f[mt], bA1 + a_off + mt * (16 * PITCH));
            ldm_x4(a2f[mt], bA2 + a_off + mt * (16 * PITCH));
        }
#pragma unroll
        for (int np = 0; np < 2; ++np) {
            uint32_t t[4];
            ldm_x4(t, bB1 + b_off + np * (16 * PITCH));
            bf1[2 * np][0] = t[0]; bf1[2 * np][1] = t[1];
            bf1[2 * np + 1][0] = t[2]; bf1[2 * np + 1][1] = t[3];
            ldm_x4(t, bB2 + b_off + np * (16 * PITCH));
            bf2[2 * np][0] = t[0]; bf2[2 * np][1] = t[1];
            bf2[2 * np + 1][0] = t[2]; bf2[2 * np + 1][1] = t[3];
        }
        // P1: q1*q1 (8 independent IMMAs)
#pragma unroll
        for (int mt = 0; mt < 2; ++mt)
#pragma unroll
            for (int nt = 0; nt < 4; ++nt)
                imma16832(acc1[mt][nt], a1f[mt], bf1[nt]);
        // P2: q1*q2 + q2*q1 (8-apart accumulator reuse)
#pragma unroll
        for (int mt = 0; mt < 2; ++mt)
#pragma unroll
            for (int nt = 0; nt < 4; ++nt)
                imma16832(acc2[mt][nt], a1f[mt], bf2[nt]);
#pragma unroll
        for (int mt = 0; mt < 2; ++mt)
#pragma unroll
            for (int nt = 0; nt < 4; ++nt)
                imma16832(acc2[mt][nt], a2f[mt], bf1[nt]);
        // P4: q2*q2 (exactness pass)
#pragma unroll
        for (int mt = 0; mt < 2; ++mt)
#pragma unroll
            for (int nt = 0; nt < 4; ++nt)
                imma16832(acc4[mt][nt], a2f[mt], bf2[nt]);
    }
    __syncthreads();

    // --- Combine digits + scales, stage fp32 tile (pitch 66) ---
    float sAr[2][2];
#pragma unroll
    for (int mt = 0; mt < 2; ++mt)
#pragma unroll
        for (int h = 0; h < 2; ++h) {
            const int row = wm * 32 + mt * 16 + gID + h * 8;
            sAr[mt][h] = SAARR ? sA[m0 + row] : INV127;
        }
    const float* sBp = sB + ((SBARR && BPC) ? ((size_t)blockIdx.z * 1024) : 0);
    float sBc[4][2];
#pragma unroll
    for (int nt = 0; nt < 4; ++nt)
#pragma unroll
        for (int b = 0; b < 2; ++b) {
            const int col = wn * 32 + nt * 8 + 2 * tg + b;
            sBc[nt][b] = SBARR ? sBp[n0 + col] : INV127;
        }

    float* F = (float*)smem;
#pragma unroll
    for (int mt = 0; mt < 2; ++mt)
#pragma unroll
        for (int nt = 0; nt < 4; ++nt)
#pragma unroll
            for (int r = 0; r < 4; ++r) {
                const int rr = wm * 32 + mt * 16 + gID + (r >= 2 ? 8 : 0);
                const int cc = wn * 32 + nt * 8 + 2 * tg + (r & 1);
                const float p = (float)acc1[mt][nt][r]
                              + ((float)acc2[mt][nt][r]
                                 + (float)acc4[mt][nt][r] * INV254) * INV254;
                F[rr * 66 + cc] = p * sAr[mt][r >= 2 ? 1 : 0] * sBc[nt][r & 1];
            }
    __syncthreads();

    // --- Final pass: bias/act/quantize or residual-add, coalesced stores ---
    {
        const int r = tid >> 1;
        const int cb = (tid & 1) * 32;
        const float* Frow = F + r * 66 + cb;
        const size_t ob = cOff + (size_t)(m0 + r) * 1024 + n0 + cb;
        const int jb = n0 + cb;

        float v[32];
#pragma unroll
        for (int j = 0; j < 32; ++j) {
            float t = Frow[j];
            if (EPI >= 1) t += bias[jb + j];
            v[j] = actf(t);
        }
        if (EPI == 2) {
            union { uint4 u; s8 b[16]; } r1a, r1b, r2a, r2b;
            r1a.u = *(const uint4*)(Rq1 + ob);
            r1b.u = *(const uint4*)(Rq1 + ob + 16);
            r2a.u = *(const uint4*)(Rq2 + ob);
            r2b.u = *(const uint4*)(Rq2 + ob + 16);
#pragma unroll
            for (int j = 0; j < 16; ++j) {
                v[j]      += ((float)r1a.b[j] + (float)r2a.b[j] * INV254) * INV127;
                v[j + 16] += ((float)r1b.b[j] + (float)r2b.b[j] * INV254) * INV127;
            }
#pragma unroll
            for (int q = 0; q < 8; ++q) {
                float4 o;
                o.x = v[q * 4 + 0]; o.y = v[q * 4 + 1];
                o.z = v[q * 4 + 2]; o.w = v[q * 4 + 3];
                *(float4*)(Of + ob + q * 4) = o;
            }
        } else {
            union { uint4 u; s8 b[16]; } o1a, o1b, o2a, o2b;
#pragma unroll
            for (int j = 0; j < 16; ++j) {
                quant2(v[j], 127.0f, o1a.b[j], o2a.b[j]);
                quant2(v[j + 16], 127.0f, o1b.b[j], o2b.b[j]);
            }
            *(uint4*)(Oq1 + ob) = o1a.u;
            *(uint4*)(Oq1 + ob + 16) = o1b.u;
            *(uint4*)(Oq2 + ob) = o2a.u;
            *(uint4*)(Oq2 + ob + 16) = o2b.u;
        }
    }
}

// ---------------------------------------------------------------------------
// Host launcher
// ---------------------------------------------------------------------------
extern "C" void kernel_launch(void* const* d_in, const int* in_sizes, int n_in,
                              void* d_out, int out_size)
{
    (void)in_sizes; (void)n_in; (void)out_size;
    const float* x       = (const float*)d_in[0];
    const float* p_mask  = (const float*)d_in[1];
    const float* Wp      = (const float*)d_in[2];
    const float* Wp_diag = (const float*)d_in[3];
    const float* Wzp     = (const float*)d_in[4];
    const float* p_lin_w = (const float*)d_in[5];
    const float* p_lin_b = (const float*)d_in[6];
    const float* z_lin_w = (const float*)d_in[7];
    const float* z_lin_b = (const float*)d_in[8];
    float* out = (float*)d_out;

    s8 *xq1, *xq2, *b1q1, *b1q2, *pq1, *pq2;
    s8 *wpq1, *wpq2, *plq1, *plq2, *wzq1, *wzq2, *zlq1, *zlq2;
    float *swp, *spl, *swz, *szl, *sxs, *sxi;
    cudaGetSymbolAddress((void**)&xq1, g_xq1);   cudaGetSymbolAddress((void**)&xq2, g_xq2);
    cudaGetSymbolAddress((void**)&b1q1, g_b1q1); cudaGetSymbolAddress((void**)&b1q2, g_b1q2);
    cudaGetSymbolAddress((void**)&pq1, g_pq1);   cudaGetSymbolAddress((void**)&pq2, g_pq2);
    cudaGetSymbolAddress((void**)&wpq1, g_wpq1); cudaGetSymbolAddress((void**)&wpq2, g_wpq2);
    cudaGetSymbolAddress((void**)&plq1, g_plq1); cudaGetSymbolAddress((void**)&plq2, g_plq2);
    cudaGetSymbolAddress((void**)&wzq1, g_wzq1); cudaGetSymbolAddress((void**)&wzq2, g_wzq2);
    cudaGetSymbolAddress((void**)&zlq1, g_zlq1); cudaGetSymbolAddress((void**)&zlq2, g_zlq2);
    cudaGetSymbolAddress((void**)&swp, g_swp);   cudaGetSymbolAddress((void**)&spl, g_spl);
    cudaGetSymbolAddress((void**)&swz, g_swz);   cudaGetSymbolAddress((void**)&szl, g_szl);
    cudaGetSymbolAddress((void**)&sxs, g_sxs);   cudaGetSymbolAddress((void**)&sxi, g_sxi);

    const int SMEM = NSTAGE * STAGE_B;  // 55296 (>= epilogue staging 128*66*4 = 33792)
    cudaFuncSetAttribute(gemm_imma<0,1,1,0,1,1>, cudaFuncAttributeMaxDynamicSharedMemorySize, SMEM);
    cudaFuncSetAttribute(gemm_imma<1,0,0,1,0,1>, cudaFuncAttributeMaxDynamicSharedMemorySize, SMEM);
    cudaFuncSetAttribute(gemm_imma<0,1,0,0,1,0>, cudaFuncAttributeMaxDynamicSharedMemorySize, SMEM);
    cudaFuncSetAttribute(gemm_imma<1,0,0,2,0,1>, cudaFuncAttributeMaxDynamicSharedMemorySize, SMEM);

    // Prep: quantize weights, compute x scales, build quantized xT
    quant_w_kernel<1><<<H_DIM, 256>>>(Wp, Wp_diag, wpq1, wpq2, swp);
    quant_w_kernel<0><<<I_DIM, 256>>>(p_lin_w, nullptr, plq1, plq2, spl);
    quant_w_kernel<0><<<H_DIM, 256>>>(Wzp, nullptr, wzq1, wzq2, swz);
    quant_w_kernel<0><<<I_DIM, 256>>>(z_lin_w, nullptr, zlq1, zlq2, szl);
    scale_x_kernel<<<dim3(4, C_DIM), 256>>>(x, p_mask, sxs, sxi);
    convT_xq_kernel<<<dim3(32, 32, C_DIM), dim3(32, 8)>>>(x, p_mask, sxi, xq1, xq2);

    const dim3 gg(16, 8, C_DIM);
    // Stage 1: b1 = act(Wp_eff @ pset)   [A=Wp(swp), B=xT(sx per-ch), triangular]
    gemm_imma<0,1,1,0,1,1><<<gg, 256, SMEM>>>(wpq1, wpq2, xq1, xq2, swp, sxs,
                                              nullptr, nullptr, nullptr,
                                              b1q1, b1q2, nullptr);
    // Stage 2: p = act(b1 @ p_lin_w^T + b)   [A=b1(1/127), B=plin(spl)]
    gemm_imma<1,0,0,1,0,1><<<gg, 256, SMEM>>>(b1q1, b1q2, plq1, plq2, nullptr, spl,
                                              p_lin_b, nullptr, nullptr,
                                              pq1, pq2, nullptr);
    // Transpose p digits for stage 3 (into b1 planes, now dead)
    transP_q_kernel<<<dim3(32, 32, C_DIM), dim3(32, 8)>>>(pq1, pq2, b1q1, b1q2);
    // Stage 3: z = act(Wzp @ p)   [A=Wzp(swz), B=pT(1/127)] -> xq planes (dead)
    gemm_imma<0,1,0,0,1,0><<<gg, 256, SMEM>>>(wzq1, wzq2, b1q1, b1q2, swz, nullptr,
                                              nullptr, nullptr, nullptr,
                                              xq1, xq2, nullptr);
    // Stage 4: out = p + act(z @ z_lin_w^T + b)   [A=z(1/127), B=zlin(szl)]
    gemm_imma<1,0,0,2,0,1><<<gg, 256, SMEM>>>(xq1, xq2, zlq1, zlq2, nullptr, szl,
                                              z_lin_b, pq1, pq2,
                                              nullptr, nullptr, out);
}

// round 14
// speedup vs baseline: 3.9800x; 3.9800x over previous
#include <cuda_runtime.h>
#include <cuda_fp16.h>
#include <cstdint>
#include <cstddef>

#define H_DIM 1024
#define I_DIM 1024
#define C_DIM 64

// ---------------------------------------------------------------------------
// Static scratch (module-load allocated). 256B-aligned for 16B vector access.
// fp16 hi/lo digit planes.
// ---------------------------------------------------------------------------
#define ACT_ELEMS ((size_t)C_DIM * H_DIM * I_DIM)
__device__ __align__(256) __half g_xth[ACT_ELEMS];   // xT hi (later z hi)
__device__ __align__(256) __half g_xtl[ACT_ELEMS];   // xT lo
__device__ __align__(256) __half g_b1h[ACT_ELEMS];   // b1 hi (later pT hi)
__device__ __align__(256) __half g_ph[ACT_ELEMS];    // p hi
__device__ __align__(256) __half g_pl[ACT_ELEMS];    // p lo (stage-4 residual)
__device__ __align__(256) __half g_wph[H_DIM * H_DIM];
__device__ __align__(256) __half g_wpl[H_DIM * H_DIM];
__device__ __align__(256) __half g_plh[I_DIM * I_DIM];
__device__ __align__(256) __half g_pll[I_DIM * I_DIM];
__device__ __align__(256) __half g_wzh[H_DIM * H_DIM];
__device__ __align__(256) __half g_wzl[H_DIM * H_DIM];
__device__ __align__(256) __half g_zlh[I_DIM * I_DIM];
__device__ __align__(256) __half g_zll[I_DIM * I_DIM];

__device__ __forceinline__ float actf(float x) { return fminf(fmaxf(x, -1.0f), 1.0f); }

__device__ __forceinline__ void split_h(float v, __half& hi, __half& lo) {
    hi = __float2half_rn(v);
    lo = __float2half_rn(v - __half2float(hi));
}

// ---------------------------------------------------------------------------
// Prep kernels
// ---------------------------------------------------------------------------
__global__ void prep_wp_kernel(const float* __restrict__ Wp, const float* __restrict__ Wd,
                               __half* __restrict__ Oh, __half* __restrict__ Ol) {
    const int h = blockIdx.x;
    const float dv = Wd[h];
#pragma unroll
    for (int j = 0; j < 4; ++j) {
        const int k = threadIdx.x + j * 256;
        float v = Wp[h * 1024 + k];
        if (k > h) v = 0.0f;
        else if (k == h) v = fminf(fmaxf(v, 0.0f), 1.0f) + dv;
        __half hi, lo; split_h(v, hi, lo);
        Oh[h * 1024 + k] = hi;
        Ol[h * 1024 + k] = lo;
    }
}

__global__ void conv_mat_kernel(const float* __restrict__ W,
                                __half* __restrict__ Oh, __half* __restrict__ Ol) {
    const int i4 = (blockIdx.x * 256 + threadIdx.x) * 4;
    const float4 v = *(const float4*)(W + i4);
    const float vv[4] = {v.x, v.y, v.z, v.w};
    union { uint2 u; __half b[4]; } ph, pl;
#pragma unroll
    for (int e = 0; e < 4; ++e) { split_h(vv[e], ph.b[e], pl.b[e]); }
    *(uint2*)(Oh + i4) = ph.u;
    *(uint2*)(Ol + i4) = pl.u;
}

// XT[c,i,k] = x[c,k,i] * act(pm[k,i]) -> fp16 hi/lo
__global__ void convT_x_kernel(const float* __restrict__ x, const float* __restrict__ pm,
                               __half* __restrict__ Th, __half* __restrict__ Tl) {
    __shared__ float t[32][33];
    const int i0 = blockIdx.x * 32, k0 = blockIdx.y * 32;
    const size_t cOff = (size_t)blockIdx.z << 20;
    const int tx = threadIdx.x, ty = threadIdx.y;
#pragma unroll
    for (int r = 0; r < 4; ++r) {
        const int k = k0 + ty + r * 8;
        const float m = actf(pm[(size_t)k * 1024 + i0 + tx]);
        t[ty + r * 8][tx] = x[cOff + (size_t)k * 1024 + i0 + tx] * m;
    }
    __syncthreads();
#pragma unroll
    for (int r = 0; r < 4; ++r) {
        const int i = i0 + ty + r * 8;
        const float v = t[tx][ty + r * 8];
        __half hi, lo; split_h(v, hi, lo);
        Th[cOff + (size_t)i * 1024 + k0 + tx] = hi;
        Tl[cOff + (size_t)i * 1024 + k0 + tx] = lo;
    }
}

// Single-plane fp16 transpose: T[c,i,h] = P[c,h,i]
__global__ void transP_h_kernel(const __half* __restrict__ P, __half* __restrict__ T) {
    __shared__ __half t[32][34];
    const int i0 = blockIdx.x * 32, h0 = blockIdx.y * 32;
    const size_t cOff = (size_t)blockIdx.z << 20;
    const int tx = threadIdx.x, ty = threadIdx.y;
#pragma unroll
    for (int r = 0; r < 4; ++r) {
        const int h = h0 + ty + r * 8;
        t[ty + r * 8][tx] = P[cOff + (size_t)h * 1024 + i0 + tx];
    }
    __syncthreads();
#pragma unroll
    for (int r = 0; r < 4; ++r) {
        const int i = i0 + ty + r * 8;
        T[cOff + (size_t)i * 1024 + h0 + tx] = t[tx][ty + r * 8];
    }
}

// ---------------------------------------------------------------------------
// mma.sync / ldmatrix / cp.async helpers (base ISA, valid on target sm_103)
// ---------------------------------------------------------------------------
__device__ __forceinline__ void mma16816(float* d, const uint32_t* a, const uint32_t* b) {
    asm volatile(
        "mma.sync.aligned.m16n8k16.row.col.f32.f16.f16.f32 "
        "{%0,%1,%2,%3}, {%4,%5,%6,%7}, {%8,%9}, {%0,%1,%2,%3};"
        : "+f"(d[0]), "+f"(d[1]), "+f"(d[2]), "+f"(d[3])
        : "r"(a[0]), "r"(a[1]), "r"(a[2]), "r"(a[3]), "r"(b[0]), "r"(b[1]));
}
__device__ __forceinline__ void ldm_x4(uint32_t* r, uint32_t addr) {
    asm volatile("ldmatrix.sync.aligned.m8n8.x4.shared.b16 {%0,%1,%2,%3}, [%4];"
                 : "=r"(r[0]), "=r"(r[1]), "=r"(r[2]), "=r"(r[3]) : "r"(addr));
}
__device__ __forceinline__ void cp16(uint32_t dst, const void* src) {
    asm volatile("cp.async.cg.shared.global [%0], [%1], 16;" :: "r"(dst), "l"(src) : "memory");
}
__device__ __forceinline__ uint32_t smem_u32(const void* p) {
    uint32_t a;
    asm("{ .reg .u64 t; cvta.to.shared.u64 t, %1; cvt.u32.u64 %0, t; }" : "=r"(a) : "l"(p));
    return a;
}

// ---------------------------------------------------------------------------
// fp16 split GEMM: D[m,n] = sum_k A[m,k]*B[n,k] (both K-contiguous).
// Passes: Ah*Bh always; +Ah*Bl if BLO; +Al*Bh if ALO. fp32 accum.
// Tile 128x128, BK=32, 8 warps (64x32 each), 3-stage cp.async pipeline,
// 80B-pitch smem (conflict-free ldmatrix), 16 independent HMMAs per pass.
// APC/BPC: per-channel operand. TRI: triangular k-skip (stage 1).
// EPI: 0 = act -> hi(+lo if OLO); 1 = +bias; 2 = act(+bias)+residual -> f32.
// ---------------------------------------------------------------------------
#define TILE_B 10240        // 128 rows * 80 bytes
#define BUF_B  (4 * TILE_B) // slots: Ah, Al, Bh, Bl
#define NSTAGE 3

template <int APC, int BPC, int TRI, int EPI, int ALO, int BLO, int OLO>
__global__ __launch_bounds__(256, 1)
void gemm_mma(const __half* __restrict__ Ah, const __half* __restrict__ Al,
              const __half* __restrict__ Bh, const __half* __restrict__ Bl,
              const float* __restrict__ bias,
              const __half* __restrict__ Rh, const __half* __restrict__ Rl,
              __half* __restrict__ Oh, __half* __restrict__ Ol,
              float* __restrict__ Of)
{
    extern __shared__ char smem[];
    const uint32_t sb = smem_u32(smem);
    const int tid = threadIdx.x;
    const int wid = tid >> 5;
    const int lane = tid & 31;
    const int gID = lane >> 2;
    const int tg  = lane & 3;
    const int warp_m = wid & 1;
    const int warp_n = wid >> 1;
    const int n0 = blockIdx.x * 128;
    const int m0 = blockIdx.y * 128;
    const size_t cOff = (size_t)blockIdx.z << 20;

    const int nch = TRI ? (blockIdx.y + 1) * 4 : 32;   // BK=32 chunks

    const __half* pAh = Ah + (APC ? cOff : 0) + (size_t)m0 * 1024;
    const __half* pAl = ALO ? (Al + (APC ? cOff : 0) + (size_t)m0 * 1024) : nullptr;
    const __half* pBh = Bh + (BPC ? cOff : 0) + (size_t)n0 * 1024;
    const __half* pBl = BLO ? (Bl + (BPC ? cOff : 0) + (size_t)n0 * 1024) : nullptr;

    auto issue = [&](int kc, int st) {
        const uint32_t base = sb + st * BUF_B;
#pragma unroll
        for (int i = 0; i < 2; ++i) {
            const int u = tid + i * 256;
            const int row = u >> 2;
            const int c16 = u & 3;
            const uint32_t doff = row * 80 + c16 * 16;
            const size_t so = (size_t)row * 1024 + kc * 32 + c16 * 8;
            cp16(base + doff, pAh + so);
            if (ALO) cp16(base + TILE_B + doff, pAl + so);
            cp16(base + 2 * TILE_B + doff, pBh + so);
            if (BLO) cp16(base + 3 * TILE_B + doff, pBl + so);
        }
        asm volatile("cp.async.commit_group;" ::: "memory");
    };

    const uint32_t a_off = (uint32_t)((warp_m * 64 + (lane & 7) + ((lane >> 3) & 1) * 8) * 80
                                      + (lane >> 4) * 16);
    const uint32_t b_off = (uint32_t)((warp_n * 32 + (lane & 7) + ((lane >> 4) & 1) * 8) * 80
                                      + ((lane >> 3) & 1) * 16);

    float acc[4][4][4];
#pragma unroll
    for (int mt = 0; mt < 4; ++mt)
#pragma unroll
        for (int nt = 0; nt < 4; ++nt)
#pragma unroll
            for (int r = 0; r < 4; ++r) acc[mt][nt][r] = 0.0f;

    issue(0, 0);
    issue(1, 1);

    for (int kc = 0; kc < nch; ++kc) {
        if (kc + 1 < nch) {
            asm volatile("cp.async.wait_group 1;" ::: "memory");
        } else {
            asm volatile("cp.async.wait_group 0;" ::: "memory");
        }
        __syncthreads();
        if (kc + 2 < nch) issue(kc + 2, (kc + 2) % NSTAGE);

        const uint32_t bAh = sb + (kc % NSTAGE) * BUF_B;
        const uint32_t bAl = bAh + TILE_B;
        const uint32_t bBh = bAh + 2 * TILE_B;
        const uint32_t bBl = bAh + 3 * TILE_B;

#pragma unroll
        for (int ks = 0; ks < 2; ++ks) {
            const uint32_t ko = ks * 32;
            uint32_t ah[4][4], al[4][4], bhf[4][2], blf[4][2];
#pragma unroll
            for (int mt = 0; mt < 4; ++mt) {
                ldm_x4(ah[mt], bAh + a_off + mt * 1280 + ko);
                if (ALO) ldm_x4(al[mt], bAl + a_off + mt * 1280 + ko);
            }
#pragma unroll
            for (int np = 0; np < 2; ++np) {
                uint32_t t0[4];
                ldm_x4(t0, bBh + b_off + np * 1280 + ko);
                bhf[2 * np][0] = t0[0]; bhf[2 * np][1] = t0[1];
                bhf[2 * np + 1][0] = t0[2]; bhf[2 * np + 1][1] = t0[3];
                if (BLO) {
                    uint32_t t1[4];
                    ldm_x4(t1, bBl + b_off + np * 1280 + ko);
                    blf[2 * np][0] = t1[0]; blf[2 * np][1] = t1[1];
                    blf[2 * np + 1][0] = t1[2]; blf[2 * np + 1][1] = t1[3];
                }
            }
            // Pass 1: Ah*Bh (16 independent HMMAs)
#pragma unroll
            for (int mt = 0; mt < 4; ++mt)
#pragma unroll
                for (int nt = 0; nt < 4; ++nt)
                    mma16816(acc[mt][nt], ah[mt], bhf[nt]);
            // Pass 2: Ah*Bl
            if (BLO) {
#pragma unroll
                for (int mt = 0; mt < 4; ++mt)
#pragma unroll
                    for (int nt = 0; nt < 4; ++nt)
                        mma16816(acc[mt][nt], ah[mt], blf[nt]);
            }
            // Pass 3: Al*Bh
            if (ALO) {
#pragma unroll
                for (int mt = 0; mt < 4; ++mt)
#pragma unroll
                    for (int nt = 0; nt < 4; ++nt)
                        mma16816(acc[mt][nt], al[mt], bhf[nt]);
            }
        }
    }
    __syncthreads();

    // --- Epilogue: stage fp32 tile in smem (pitch 129), then coalesced stores ---
    float* F = (float*)smem;
#pragma unroll
    for (int mt = 0; mt < 4; ++mt)
#pragma unroll
        for (int nt = 0; nt < 4; ++nt)
#pragma unroll
            for (int r = 0; r < 4; ++r) {
                const int rr = warp_m * 64 + mt * 16 + gID + (r >= 2 ? 8 : 0);
                const int cc = warp_n * 32 + nt * 8 + 2 * tg + (r & 1);
                F[rr * 129 + cc] = acc[mt][nt][r];
            }
    __syncthreads();

    {
        const int r  = tid >> 1;
        const int hf = tid & 1;
        const float* Frow = F + r * 129 + hf * 64;
        const size_t ob = cOff + (size_t)(m0 + r) * 1024 + n0 + hf * 64;
        const int jb = n0 + hf * 64;

        float bj[64];
        if (EPI >= 1) {
#pragma unroll
            for (int e4 = 0; e4 < 16; ++e4) {
                const float4 bv = *(const float4*)(bias + jb + e4 * 4);
                bj[e4 * 4 + 0] = bv.x; bj[e4 * 4 + 1] = bv.y;
                bj[e4 * 4 + 2] = bv.z; bj[e4 * 4 + 3] = bv.w;
            }
        }

#pragma unroll
        for (int g = 0; g < 8; ++g) {
            float v[8];
#pragma unroll
            for (int e = 0; e < 8; ++e) {
                float t = Frow[g * 8 + e];
                if (EPI >= 1) t += bj[g * 8 + e];
                v[e] = actf(t);
            }
            if (EPI == 2) {
                union { uint4 u; __half b[8]; } rh, rl;
                rh.u = *(const uint4*)(Rh + ob + g * 8);
                rl.u = *(const uint4*)(Rl + ob + g * 8);
                float4 o0, o1;
                o0.x = v[0] + __half2float(rh.b[0]) + __half2float(rl.b[0]);
                o0.y = v[1] + __half2float(rh.b[1]) + __half2float(rl.b[1]);
                o0.z = v[2] + __half2float(rh.b[2]) + __half2float(rl.b[2]);
                o0.w = v[3] + __half2float(rh.b[3]) + __half2float(rl.b[3]);
                o1.x = v[4] + __half2float(rh.b[4]) + __half2float(rl.b[4]);
                o1.y = v[5] + __half2float(rh.b[5]) + __half2float(rl.b[5]);
                o1.z = v[6] + __half2float(rh.b[6]) + __half2float(rl.b[6]);
                o1.w = v[7] + __half2float(rh.b[7]) + __half2float(rl.b[7]);
                *(float4*)(Of + ob + g * 8)     = o0;
                *(float4*)(Of + ob + g * 8 + 4) = o1;
            } else {
                union { uint4 u; __half b[8]; } oh_, ol_;
#pragma unroll
                for (int e = 0; e < 8; ++e) split_h(v[e], oh_.b[e], ol_.b[e]);
                *(uint4*)(Oh + ob + g * 8) = oh_.u;
                if (OLO) *(uint4*)(Ol + ob + g * 8) = ol_.u;
            }
        }
    }
}

// ---------------------------------------------------------------------------
// Host launcher
// ---------------------------------------------------------------------------
extern "C" void kernel_launch(void* const* d_in, const int* in_sizes, int n_in,
                              void* d_out, int out_size)
{
    (void)in_sizes; (void)n_in; (void)out_size;
    const float* x       = (const float*)d_in[0];
    const float* p_mask  = (const float*)d_in[1];
    const float* Wp      = (const float*)d_in[2];
    const float* Wp_diag = (const float*)d_in[3];
    const float* Wzp     = (const float*)d_in[4];
    const float* p_lin_w = (const float*)d_in[5];
    const float* p_lin_b = (const float*)d_in[6];
    const float* z_lin_w = (const float*)d_in[7];
    const float* z_lin_b = (const float*)d_in[8];
    float* out = (float*)d_out;

    __half *xth, *xtl, *b1h, *ph, *pl;
    __half *wph, *wpl, *plh, *pll, *wzh, *wzl, *zlh, *zll;
    cudaGetSymbolAddress((void**)&xth, g_xth); cudaGetSymbolAddress((void**)&xtl, g_xtl);
    cudaGetSymbolAddress((void**)&b1h, g_b1h);
    cudaGetSymbolAddress((void**)&ph,  g_ph);  cudaGetSymbolAddress((void**)&pl,  g_pl);
    cudaGetSymbolAddress((void**)&wph, g_wph); cudaGetSymbolAddress((void**)&wpl, g_wpl);
    cudaGetSymbolAddress((void**)&plh, g_plh); cudaGetSymbolAddress((void**)&pll, g_pll);
    cudaGetSymbolAddress((void**)&wzh, g_wzh); cudaGetSymbolAddress((void**)&wzl, g_wzl);
    cudaGetSymbolAddress((void**)&zlh, g_zlh); cudaGetSymbolAddress((void**)&zll, g_zll);

    const int SMEM = NSTAGE * BUF_B;  // 122880 (>= epilogue staging 128*129*4)
    cudaFuncSetAttribute(gemm_mma<0,1,1,0,1,1,0>, cudaFuncAttributeMaxDynamicSharedMemorySize, SMEM);
    cudaFuncSetAttribute(gemm_mma<1,0,0,1,0,1,1>, cudaFuncAttributeMaxDynamicSharedMemorySize, SMEM);
    cudaFuncSetAttribute(gemm_mma<0,1,0,0,1,0,0>, cudaFuncAttributeMaxDynamicSharedMemorySize, SMEM);
    cudaFuncSetAttribute(gemm_mma<1,0,0,2,0,1,0>, cudaFuncAttributeMaxDynamicSharedMemorySize, SMEM);

    // Prep: fp16 hi/lo weight splits + masked/transposed x
    prep_wp_kernel<<<H_DIM, 256>>>(Wp, Wp_diag, wph, wpl);
    conv_mat_kernel<<<1024, 256>>>(p_lin_w, plh, pll);
    conv_mat_kernel<<<1024, 256>>>(Wzp, wzh, wzl);
    conv_mat_kernel<<<1024, 256>>>(z_lin_w, zlh, zll);
    convT_x_kernel<<<dim3(32, 32, C_DIM), dim3(32, 8)>>>(x, p_mask, xth, xtl);

    const dim3 gg(8, 8, C_DIM);
    // Stage 1 (3-pass): b1 = act(Wp_eff @ pset); store hi only (b1 ~96% saturated)
    gemm_mma<0,1,1,0,1,1,0><<<gg, 256, SMEM>>>(wph, wpl, xth, xtl,
                                               nullptr, nullptr, nullptr,
                                               b1h, nullptr, nullptr);
    // Stage 2 (2-pass, A hi-only): p = act(b1 @ p_lin_w^T + b); store hi+lo
    gemm_mma<1,0,0,1,0,1,1><<<gg, 256, SMEM>>>(b1h, nullptr, plh, pll,
                                               p_lin_b, nullptr, nullptr,
                                               ph, pl, nullptr);
    // Transpose p hi-plane for stage 3 (into b1h, now dead)
    transP_h_kernel<<<dim3(32, 32, C_DIM), dim3(32, 8)>>>(ph, b1h);
    // Stage 3 (2-pass, B hi-only): z = act(Wzp @ p); store hi only -> xth (dead)
    gemm_mma<0,1,0,0,1,0,0><<<gg, 256, SMEM>>>(wzh, wzl, b1h, nullptr,
                                               nullptr, nullptr, nullptr,
                                               xth, nullptr, nullptr);
    // Stage 4 (2-pass, A hi-only): out = p + act(z @ z_lin_w^T + b)
    gemm_mma<1,0,0,2,0,1,0><<<gg, 256, SMEM>>>(xth, nullptr, zlh, zll,
                                               z_lin_b, ph, pl,
                                               nullptr, nullptr, out);
}